// round 6
// baseline (speedup 1.0000x reference)
#include <cuda_runtime.h>
#include <cuda_bf16.h>
#include <math.h>

// Problem constants
#define BATCH   32
#define S_NEW   8
#define S_CACHE 4096
#define S_TOT   4104            // 4096 + 8
#define DIM     1024
#define M_ROWS  (BATCH * S_NEW) // 256
#define SPLITS  16
#define CHUNK   ((S_TOT + SPLITS - 1) / SPLITS)   // 257
#define NSLICE  (2 * SPLITS)                      // 32 partial slices

// Scratch (allocation-free rule: __device__ globals)
__device__ float g_q[M_ROWS * DIM];                 // 1 MB   q_new
__device__ float g_scores[M_ROWS * S_TOT];          // ~4.2 MB scores -> probs
__device__ float g_part[NSLICE * M_ROWS * DIM];     // 32 MB  split-K partials

// ---------------------------------------------------------------------------
// Kernel 1: projections. C[m][n] = x[m][:] . W[:][n] + b[n]
// grid (16, 4, 3): z selects Q/K/V. 64x64 tile, BK=16, 256 thr, 4x4 microtile.
// Q -> g_q. K/V new rows -> tails of keys/values output regions.
// ---------------------------------------------------------------------------
__global__ void proj_kernel(const float* __restrict__ x,
                            const float* __restrict__ Wq, const float* __restrict__ bq,
                            const float* __restrict__ Wk, const float* __restrict__ bk,
                            const float* __restrict__ Wv, const float* __restrict__ bv,
                            float* __restrict__ keys, float* __restrict__ values)
{
    const int z = blockIdx.z;
    const float* W    = (z == 0) ? Wq : (z == 1) ? Wk : Wv;
    const float* bias = (z == 0) ? bq : (z == 1) ? bk : bv;

    __shared__ float xs[64][17];
    __shared__ float ws[16][64];

    const int tid = threadIdx.x;
    const int tx = tid & 15, ty = tid >> 4;
    const int m0 = blockIdx.y * 64, n0 = blockIdx.x * 64;

    float acc[4][4] = {};

    for (int k0 = 0; k0 < DIM; k0 += 16) {
        {   // x tile 64x16
            int r = tid >> 2;
            int c = (tid & 3) * 4;
            float4 v = *(const float4*)(x + (size_t)(m0 + r) * DIM + k0 + c);
            xs[r][c] = v.x; xs[r][c + 1] = v.y; xs[r][c + 2] = v.z; xs[r][c + 3] = v.w;
        }
        {   // W tile 16x64
            int r = tid >> 4;
            int c = (tid & 15) * 4;
            *(float4*)&ws[r][c] = *(const float4*)(W + (size_t)(k0 + r) * DIM + n0 + c);
        }
        __syncthreads();
        #pragma unroll
        for (int kk = 0; kk < 16; kk++) {
            float a[4];
            #pragma unroll
            for (int i = 0; i < 4; i++) a[i] = xs[ty * 4 + i][kk];
            float4 bb = *(float4*)&ws[kk][tx * 4];
            #pragma unroll
            for (int i = 0; i < 4; i++) {
                acc[i][0] += a[i] * bb.x;
                acc[i][1] += a[i] * bb.y;
                acc[i][2] += a[i] * bb.z;
                acc[i][3] += a[i] * bb.w;
            }
        }
        __syncthreads();
    }

    #pragma unroll
    for (int i = 0; i < 4; i++) {
        int m = m0 + ty * 4 + i;
        #pragma unroll
        for (int j = 0; j < 4; j++) {
            int n = n0 + tx * 4 + j;
            float val = acc[i][j] + bias[n];
            if (z == 0) {
                g_q[(size_t)m * DIM + n] = val;
            } else {
                int b = m >> 3, s = m & 7;
                float* dst = (z == 1) ? keys : values;
                dst[(size_t)b * S_TOT * DIM + (size_t)(S_CACHE + s) * DIM + n] = val;
            }
        }
    }
}

// ---------------------------------------------------------------------------
// Kernel 2: fused key-cache copy + scores. Each warp handles 4 key rows
// SIMULTANEOUSLY so each smem q-load is amortized over 4 rows (kills the
// smem-crossbar bottleneck: smem traffic = 2x DRAM instead of 8x).
// grid (ceil(S_TOT/32), BATCH), 256 thr = 8 warps x 4 rows = 32 rows/block.
// ---------------------------------------------------------------------------
__global__ void __launch_bounds__(256)
scores_kernel(const float* __restrict__ key_cache,
              float* __restrict__ keys)
{
    const int b    = blockIdx.y;
    const int tid  = threadIdx.x;
    const int warp = tid >> 5, lane = tid & 31;
    const int row0 = blockIdx.x * 32 + warp * 4;

    __shared__ float4 qs4[S_NEW * 256];   // 8 queries x 1024 floats = 32 KB
    {
        const float4* qsrc = (const float4*)(g_q + (size_t)b * S_NEW * DIM);
        for (int i = tid; i < S_NEW * 256; i += 256) qs4[i] = qsrc[i];
    }
    __syncthreads();

    if (row0 >= S_TOT) return;

    // per-row setup (clamped for tail safety)
    const float* krow[4];
    float*       kdst[4];
    bool valid[4], cp[4];
    #pragma unroll
    for (int r = 0; r < 4; r++) {
        int s = row0 + r;
        valid[r] = (s < S_TOT);
        int sc = valid[r] ? s : S_TOT - 1;
        cp[r] = valid[r] && (sc < S_CACHE);
        krow[r] = (sc < S_CACHE)
            ? key_cache + ((size_t)b * S_CACHE + sc) * DIM
            : keys      + ((size_t)b * S_TOT   + sc) * DIM;
        kdst[r] = keys + ((size_t)b * S_TOT + sc) * DIM;
    }

    float acc[4][S_NEW] = {};

    #pragma unroll
    for (int it = 0; it < 8; it++) {
        const int d = it * 128 + lane * 4;
        float4 kv[4];
        #pragma unroll
        for (int r = 0; r < 4; r++) {
            kv[r] = *(const float4*)(krow[r] + d);
            if (cp[r]) *(float4*)(kdst[r] + d) = kv[r];
        }
        #pragma unroll
        for (int q = 0; q < S_NEW; q++) {
            float4 qv = qs4[q * 256 + it * 32 + lane];
            #pragma unroll
            for (int r = 0; r < 4; r++) {
                acc[r][q] += kv[r].x * qv.x;
                acc[r][q] += kv[r].y * qv.y;
                acc[r][q] += kv[r].z * qv.z;
                acc[r][q] += kv[r].w * qv.w;
            }
        }
    }

    #pragma unroll
    for (int r = 0; r < 4; r++) {
        #pragma unroll
        for (int q = 0; q < S_NEW; q++) {
            float v = acc[r][q];
            #pragma unroll
            for (int off = 16; off; off >>= 1)
                v += __shfl_down_sync(0xFFFFFFFFu, v, off);
            if (lane == 0 && valid[r])
                g_scores[((size_t)b * S_NEW + q) * S_TOT + row0 + r] = v * 0.03125f;
        }
    }
}

// ---------------------------------------------------------------------------
// Kernel 3: softmax, register-resident (1 read + 1 write per element).
// One CTA of 256 threads per row; 17 elements/thread covers 4104.
// ---------------------------------------------------------------------------
#define SM_PER_T 17   // 256*17 = 4352 >= 4104
__global__ void __launch_bounds__(256)
softmax_kernel()
{
    float* p = g_scores + (size_t)blockIdx.x * S_TOT;
    const int tid = threadIdx.x;
    __shared__ float red[256];

    float val[SM_PER_T];
    float m = -1e30f;
    #pragma unroll
    for (int i = 0; i < SM_PER_T; i++) {
        int idx = tid + i * 256;
        val[i] = (idx < S_TOT) ? p[idx] : -1e30f;
        m = fmaxf(m, val[i]);
    }
    red[tid] = m; __syncthreads();
    for (int s = 128; s; s >>= 1) {
        if (tid < s) red[tid] = fmaxf(red[tid], red[tid + s]);
        __syncthreads();
    }
    m = red[0];
    __syncthreads();

    float sum = 0.f;
    #pragma unroll
    for (int i = 0; i < SM_PER_T; i++) {
        val[i] = __expf(val[i] - m);
        sum += val[i];
    }
    red[tid] = sum; __syncthreads();
    for (int s = 128; s; s >>= 1) {
        if (tid < s) red[tid] += red[tid + s];
        __syncthreads();
    }
    const float inv = 1.0f / red[0];
    #pragma unroll
    for (int i = 0; i < SM_PER_T; i++) {
        int idx = tid + i * 256;
        if (idx < S_TOT) p[idx] = val[i] * inv;
    }
}

// ---------------------------------------------------------------------------
// Kernel 4: fused value-cache copy + split-K probs @ V.
// grid (BATCH, SPLITS), 512 threads; 2 row-groups of 256; thread owns 4 cols.
// ---------------------------------------------------------------------------
__global__ void __launch_bounds__(512)
out_kernel(const float* __restrict__ value_cache,
           float* __restrict__ values)
{
    const int b    = blockIdx.x;
    const int z    = blockIdx.y;
    const int tid  = threadIdx.x;
    const int grp  = tid >> 8;
    const int col  = (tid & 255) * 4;

    const int s_beg = z * CHUNK;
    const int s_end = (s_beg + CHUNK < S_TOT) ? s_beg + CHUNK : S_TOT;
    const int s_mid = (s_end < S_CACHE) ? s_end : ((s_beg > S_CACHE) ? s_beg : S_CACHE);

    __shared__ float ps[S_NEW][CHUNK];
    {
        const float* probs = g_scores + (size_t)b * S_NEW * S_TOT;
        const int n = s_end - s_beg;
        for (int i = tid; i < S_NEW * n; i += 512) {
            int q = i / n, s = i - q * n;
            ps[q][s] = probs[(size_t)q * S_TOT + s_beg + s];
        }
    }
    __syncthreads();

    float acc[S_NEW][4] = {};

    const float* vsrc = value_cache + (size_t)b * S_CACHE * DIM + col;
    float*       vdst = values      + (size_t)b * S_TOT   * DIM + col;

    #pragma unroll 2
    for (int s = s_beg + grp; s < s_mid; s += 2) {
        float4 vv = *(const float4*)(vsrc + (size_t)s * DIM);
        *(float4*)(vdst + (size_t)s * DIM) = vv;
        #pragma unroll
        for (int q = 0; q < S_NEW; q++) {
            float pq = ps[q][s - s_beg];
            acc[q][0] += pq * vv.x;
            acc[q][1] += pq * vv.y;
            acc[q][2] += pq * vv.z;
            acc[q][3] += pq * vv.w;
        }
    }
    // tail rows (already in values, written by proj_kernel)
    for (int s = s_mid; s < s_end; s++) {
        if (((s - s_beg) & 1) != grp) continue;
        float4 vv = *(const float4*)(vdst + (size_t)s * DIM);
        #pragma unroll
        for (int q = 0; q < S_NEW; q++) {
            float pq = ps[q][s - s_beg];
            acc[q][0] += pq * vv.x;
            acc[q][1] += pq * vv.y;
            acc[q][2] += pq * vv.z;
            acc[q][3] += pq * vv.w;
        }
    }

    float* pbase = g_part + (size_t)(z * 2 + grp) * M_ROWS * DIM
                          + (size_t)b * S_NEW * DIM + col;
    #pragma unroll
    for (int q = 0; q < S_NEW; q++)
        *(float4*)(pbase + (size_t)q * DIM) = *(float4*)acc[q];
}

// ---------------------------------------------------------------------------
// Kernel 5: deterministic split-K combine.
// ---------------------------------------------------------------------------
__global__ void combine_kernel(float* __restrict__ out)
{
    const int idx = blockIdx.x * blockDim.x + threadIdx.x;
    const float4* p = (const float4*)g_part + idx;
    float4 a = {0.f, 0.f, 0.f, 0.f};
    #pragma unroll
    for (int z = 0; z < NSLICE; z++) {
        float4 v = p[(size_t)z * (M_ROWS * DIM / 4)];
        a.x += v.x; a.y += v.y; a.z += v.z; a.w += v.w;
    }
    ((float4*)out)[idx] = a;
}

// ---------------------------------------------------------------------------
extern "C" void kernel_launch(void* const* d_in, const int* in_sizes, int n_in,
                              void* d_out, int out_size)
{
    const float* input       = (const float*)d_in[0];
    const float* key_cache   = (const float*)d_in[1];
    const float* value_cache = (const float*)d_in[2];
    const float* Wk          = (const float*)d_in[3];
    const float* bk          = (const float*)d_in[4];
    const float* Wv          = (const float*)d_in[5];
    const float* bv          = (const float*)d_in[6];
    const float* Wq          = (const float*)d_in[7];
    const float* bq          = (const float*)d_in[8];

    float* out    = (float*)d_out;                                // [B, S_NEW, D]
    float* keys   = out + (size_t)BATCH * S_NEW * DIM;            // [B, S_TOT, D]
    float* values = keys + (size_t)BATCH * S_TOT * DIM;           // [B, S_TOT, D]

    // 1) projections: q -> scratch, k/v new rows -> output tails
    proj_kernel<<<dim3(16, 4, 3), 256>>>(input, Wq, bq, Wk, bk, Wv, bv, keys, values);

    // 2) fused key copy + scores (4 rows/warp)
    scores_kernel<<<dim3((S_TOT + 31) / 32, BATCH), 256>>>(key_cache, keys);

    // 3) softmax (register-resident)
    softmax_kernel<<<M_ROWS, 256>>>();

    // 4) fused value copy + split-K probs @ V
    out_kernel<<<dim3(BATCH, SPLITS), 512>>>(value_cache, values);

    // 5) deterministic combine of split-K partials
    combine_kernel<<<(M_ROWS * DIM / 4) / 256, 256>>>(out);
}

// round 7
// speedup vs baseline: 1.0063x; 1.0063x over previous
#include <cuda_runtime.h>
#include <cuda_bf16.h>
#include <math.h>

// Problem constants
#define BATCH   32
#define S_NEW   8
#define S_CACHE 4096
#define S_TOT   4104            // 4096 + 8
#define DIM     1024
#define M_ROWS  (BATCH * S_NEW) // 256
#define SPLITS  16
#define CHUNK   ((S_TOT + SPLITS - 1) / SPLITS)   // 257
#define NSLICE  (2 * SPLITS)                      // 32 partial slices

// Scratch (allocation-free rule: __device__ globals)
__device__ float g_q[M_ROWS * DIM];                 // 1 MB   q_new
__device__ float g_scores[M_ROWS * S_TOT];          // ~4.2 MB scores -> probs
__device__ float g_part[NSLICE * M_ROWS * DIM];     // 32 MB  split-K partials

// ---------------------------------------------------------------------------
// Kernel 1: projections. C[m][n] = x[m][:] . W[:][n] + b[n]
// grid (16, 4, 3): z selects Q/K/V. 64x64 tile, BK=16, 256 thr, 4x4 microtile.
// Q -> g_q. K/V new rows -> tails of keys/values output regions.
// ---------------------------------------------------------------------------
__global__ void proj_kernel(const float* __restrict__ x,
                            const float* __restrict__ Wq, const float* __restrict__ bq,
                            const float* __restrict__ Wk, const float* __restrict__ bk,
                            const float* __restrict__ Wv, const float* __restrict__ bv,
                            float* __restrict__ keys, float* __restrict__ values)
{
    const int z = blockIdx.z;
    const float* W    = (z == 0) ? Wq : (z == 1) ? Wk : Wv;
    const float* bias = (z == 0) ? bq : (z == 1) ? bk : bv;

    __shared__ float xs[64][17];
    __shared__ float ws[16][64];

    const int tid = threadIdx.x;
    const int tx = tid & 15, ty = tid >> 4;
    const int m0 = blockIdx.y * 64, n0 = blockIdx.x * 64;

    float acc[4][4] = {};

    for (int k0 = 0; k0 < DIM; k0 += 16) {
        {   // x tile 64x16
            int r = tid >> 2;
            int c = (tid & 3) * 4;
            float4 v = *(const float4*)(x + (size_t)(m0 + r) * DIM + k0 + c);
            xs[r][c] = v.x; xs[r][c + 1] = v.y; xs[r][c + 2] = v.z; xs[r][c + 3] = v.w;
        }
        {   // W tile 16x64
            int r = tid >> 4;
            int c = (tid & 15) * 4;
            *(float4*)&ws[r][c] = *(const float4*)(W + (size_t)(k0 + r) * DIM + n0 + c);
        }
        __syncthreads();
        #pragma unroll
        for (int kk = 0; kk < 16; kk++) {
            float a[4];
            #pragma unroll
            for (int i = 0; i < 4; i++) a[i] = xs[ty * 4 + i][kk];
            float4 bb = *(float4*)&ws[kk][tx * 4];
            #pragma unroll
            for (int i = 0; i < 4; i++) {
                acc[i][0] += a[i] * bb.x;
                acc[i][1] += a[i] * bb.y;
                acc[i][2] += a[i] * bb.z;
                acc[i][3] += a[i] * bb.w;
            }
        }
        __syncthreads();
    }

    #pragma unroll
    for (int i = 0; i < 4; i++) {
        int m = m0 + ty * 4 + i;
        #pragma unroll
        for (int j = 0; j < 4; j++) {
            int n = n0 + tx * 4 + j;
            float val = acc[i][j] + bias[n];
            if (z == 0) {
                g_q[(size_t)m * DIM + n] = val;
            } else {
                int b = m >> 3, s = m & 7;
                float* dst = (z == 1) ? keys : values;
                dst[(size_t)b * S_TOT * DIM + (size_t)(S_CACHE + s) * DIM + n] = val;
            }
        }
    }
}

// ---------------------------------------------------------------------------
// Kernel 2: fused key-cache copy + scores (v3).
// grid (129, BATCH): blocks 0..127 cover cache rows (32 rows each, uniform:
// copy+compute, zero per-row predicates); block 128 covers the 8 tail rows.
// 512 threads = 16 warps x 2 rows/warp. Software-pipelined loads.
// ---------------------------------------------------------------------------
__global__ void __launch_bounds__(512)
scores_kernel(const float* __restrict__ key_cache,
              float* __restrict__ keys)
{
    const int b    = blockIdx.y;
    const int tid  = threadIdx.x;
    const int warp = tid >> 5, lane = tid & 31;

    __shared__ float4 qs4[S_NEW * 256];   // 8 queries x 1024 floats = 32 KB
    {
        const float4* qsrc = (const float4*)(g_q + (size_t)b * S_NEW * DIM);
        #pragma unroll
        for (int i = 0; i < 4; i++) qs4[tid + i * 512] = qsrc[tid + i * 512];
    }
    __syncthreads();

    float acc0[S_NEW] = {}, acc1[S_NEW] = {};
    int row0;

    if (blockIdx.x < 128) {
        // ---- cache region: stream + copy + compute (uniform, no predicates)
        row0 = blockIdx.x * 32 + warp * 2;
        const float* s0 = key_cache + ((size_t)b * S_CACHE + row0) * DIM + lane * 4;
        const float* s1 = s0 + DIM;
        float* d0 = keys + ((size_t)b * S_TOT + row0) * DIM + lane * 4;
        float* d1 = d0 + DIM;

        float4 a0 = *(const float4*)s0;
        float4 a1 = *(const float4*)s1;
        #pragma unroll
        for (int it = 0; it < 8; it++) {
            float4 n0, n1;
            if (it < 7) {
                n0 = *(const float4*)(s0 + (it + 1) * 128);
                n1 = *(const float4*)(s1 + (it + 1) * 128);
            }
            *(float4*)(d0 + it * 128) = a0;
            *(float4*)(d1 + it * 128) = a1;
            #pragma unroll
            for (int q = 0; q < S_NEW; q++) {
                float4 qv = qs4[q * 256 + it * 32 + lane];
                acc0[q] += a0.x * qv.x + a0.y * qv.y + a0.z * qv.z + a0.w * qv.w;
                acc1[q] += a1.x * qv.x + a1.y * qv.y + a1.z * qv.z + a1.w * qv.w;
            }
            a0 = n0; a1 = n1;
        }
    } else {
        // ---- tail rows 4096..4103 (already in keys via proj): warps 0..3
        if (warp >= 4) return;
        row0 = S_CACHE + warp * 2;
        const float* s0 = keys + ((size_t)b * S_TOT + row0) * DIM + lane * 4;
        const float* s1 = s0 + DIM;
        #pragma unroll
        for (int it = 0; it < 8; it++) {
            float4 a0 = *(const float4*)(s0 + it * 128);
            float4 a1 = *(const float4*)(s1 + it * 128);
            #pragma unroll
            for (int q = 0; q < S_NEW; q++) {
                float4 qv = qs4[q * 256 + it * 32 + lane];
                acc0[q] += a0.x * qv.x + a0.y * qv.y + a0.z * qv.z + a0.w * qv.w;
                acc1[q] += a1.x * qv.x + a1.y * qv.y + a1.z * qv.z + a1.w * qv.w;
            }
        }
    }

    // epilogue: warp-reduce 2 rows x 8 queries, lane 0 writes
    #pragma unroll
    for (int q = 0; q < S_NEW; q++) {
        float v0 = acc0[q], v1 = acc1[q];
        #pragma unroll
        for (int off = 16; off; off >>= 1) {
            v0 += __shfl_down_sync(0xFFFFFFFFu, v0, off);
            v1 += __shfl_down_sync(0xFFFFFFFFu, v1, off);
        }
        if (lane == 0) {
            g_scores[((size_t)b * S_NEW + q) * S_TOT + row0]     = v0 * 0.03125f;
            g_scores[((size_t)b * S_NEW + q) * S_TOT + row0 + 1] = v1 * 0.03125f;
        }
    }
}

// ---------------------------------------------------------------------------
// Kernel 3: softmax, register-resident (1 read + 1 write per element).
// ---------------------------------------------------------------------------
#define SM_PER_T 17   // 256*17 = 4352 >= 4104
__global__ void __launch_bounds__(256)
softmax_kernel()
{
    float* p = g_scores + (size_t)blockIdx.x * S_TOT;
    const int tid = threadIdx.x;
    __shared__ float red[256];

    float val[SM_PER_T];
    float m = -1e30f;
    #pragma unroll
    for (int i = 0; i < SM_PER_T; i++) {
        int idx = tid + i * 256;
        val[i] = (idx < S_TOT) ? p[idx] : -1e30f;
        m = fmaxf(m, val[i]);
    }
    red[tid] = m; __syncthreads();
    for (int s = 128; s; s >>= 1) {
        if (tid < s) red[tid] = fmaxf(red[tid], red[tid + s]);
        __syncthreads();
    }
    m = red[0];
    __syncthreads();

    float sum = 0.f;
    #pragma unroll
    for (int i = 0; i < SM_PER_T; i++) {
        val[i] = __expf(val[i] - m);
        sum += val[i];
    }
    red[tid] = sum; __syncthreads();
    for (int s = 128; s; s >>= 1) {
        if (tid < s) red[tid] += red[tid + s];
        __syncthreads();
    }
    const float inv = 1.0f / red[0];
    #pragma unroll
    for (int i = 0; i < SM_PER_T; i++) {
        int idx = tid + i * 256;
        if (idx < S_TOT) p[idx] = val[i] * inv;
    }
}

// ---------------------------------------------------------------------------
// Kernel 4: fused value-cache copy + split-K probs @ V. (unchanged, 75% DRAM)
// ---------------------------------------------------------------------------
__global__ void __launch_bounds__(512)
out_kernel(const float* __restrict__ value_cache,
           float* __restrict__ values)
{
    const int b    = blockIdx.x;
    const int z    = blockIdx.y;
    const int tid  = threadIdx.x;
    const int grp  = tid >> 8;
    const int col  = (tid & 255) * 4;

    const int s_beg = z * CHUNK;
    const int s_end = (s_beg + CHUNK < S_TOT) ? s_beg + CHUNK : S_TOT;
    const int s_mid = (s_end < S_CACHE) ? s_end : ((s_beg > S_CACHE) ? s_beg : S_CACHE);

    __shared__ float ps[S_NEW][CHUNK];
    {
        const float* probs = g_scores + (size_t)b * S_NEW * S_TOT;
        const int n = s_end - s_beg;
        for (int i = tid; i < S_NEW * n; i += 512) {
            int q = i / n, s = i - q * n;
            ps[q][s] = probs[(size_t)q * S_TOT + s_beg + s];
        }
    }
    __syncthreads();

    float acc[S_NEW][4] = {};

    const float* vsrc = value_cache + (size_t)b * S_CACHE * DIM + col;
    float*       vdst = values      + (size_t)b * S_TOT   * DIM + col;

    #pragma unroll 2
    for (int s = s_beg + grp; s < s_mid; s += 2) {
        float4 vv = *(const float4*)(vsrc + (size_t)s * DIM);
        *(float4*)(vdst + (size_t)s * DIM) = vv;
        #pragma unroll
        for (int q = 0; q < S_NEW; q++) {
            float pq = ps[q][s - s_beg];
            acc[q][0] += pq * vv.x;
            acc[q][1] += pq * vv.y;
            acc[q][2] += pq * vv.z;
            acc[q][3] += pq * vv.w;
        }
    }
    for (int s = s_mid; s < s_end; s++) {
        if (((s - s_beg) & 1) != grp) continue;
        float4 vv = *(const float4*)(vdst + (size_t)s * DIM);
        #pragma unroll
        for (int q = 0; q < S_NEW; q++) {
            float pq = ps[q][s - s_beg];
            acc[q][0] += pq * vv.x;
            acc[q][1] += pq * vv.y;
            acc[q][2] += pq * vv.z;
            acc[q][3] += pq * vv.w;
        }
    }

    float* pbase = g_part + (size_t)(z * 2 + grp) * M_ROWS * DIM
                          + (size_t)b * S_NEW * DIM + col;
    #pragma unroll
    for (int q = 0; q < S_NEW; q++)
        *(float4*)(pbase + (size_t)q * DIM) = *(float4*)acc[q];
}

// ---------------------------------------------------------------------------
// Kernel 5: deterministic split-K combine.
// ---------------------------------------------------------------------------
__global__ void combine_kernel(float* __restrict__ out)
{
    const int idx = blockIdx.x * blockDim.x + threadIdx.x;
    const float4* p = (const float4*)g_part + idx;
    float4 a = {0.f, 0.f, 0.f, 0.f};
    #pragma unroll
    for (int z = 0; z < NSLICE; z++) {
        float4 v = p[(size_t)z * (M_ROWS * DIM / 4)];
        a.x += v.x; a.y += v.y; a.z += v.z; a.w += v.w;
    }
    ((float4*)out)[idx] = a;
}

// ---------------------------------------------------------------------------
extern "C" void kernel_launch(void* const* d_in, const int* in_sizes, int n_in,
                              void* d_out, int out_size)
{
    const float* input       = (const float*)d_in[0];
    const float* key_cache   = (const float*)d_in[1];
    const float* value_cache = (const float*)d_in[2];
    const float* Wk          = (const float*)d_in[3];
    const float* bk          = (const float*)d_in[4];
    const float* Wv          = (const float*)d_in[5];
    const float* bv          = (const float*)d_in[6];
    const float* Wq          = (const float*)d_in[7];
    const float* bq          = (const float*)d_in[8];

    float* out    = (float*)d_out;                                // [B, S_NEW, D]
    float* keys   = out + (size_t)BATCH * S_NEW * DIM;            // [B, S_TOT, D]
    float* values = keys + (size_t)BATCH * S_TOT * DIM;           // [B, S_TOT, D]

    // 1) projections: q -> scratch, k/v new rows -> output tails
    proj_kernel<<<dim3(16, 4, 3), 256>>>(input, Wq, bq, Wk, bk, Wv, bv, keys, values);

    // 2) fused key copy + scores (uniform blocks, 2 rows/warp, pipelined)
    scores_kernel<<<dim3(129, BATCH), 512>>>(key_cache, keys);

    // 3) softmax (register-resident)
    softmax_kernel<<<M_ROWS, 256>>>();

    // 4) fused value copy + split-K probs @ V
    out_kernel<<<dim3(BATCH, SPLITS), 512>>>(value_cache, values);

    // 5) deterministic combine of split-K partials
    combine_kernel<<<(M_ROWS * DIM / 4) / 256, 256>>>(out);
}